// round 3
// baseline (speedup 1.0000x reference)
#include <cuda_runtime.h>

// Problem shapes (fixed by the reference)
#define BB 4
#define QQ 128
#define KK 1024
#define HH 256
#define QS 256
#define KSZ 256
#define DV 256

// Scratch (alloc-free rule: __device__ globals)
__device__ float g_qproj[BB * QQ * HH];   // [B,Q,H]
__device__ float g_kproj[BB * KK * HH];   // [B,K,H]
__device__ float g_attn [BB * QQ * KK];   // [B,Q,K]

// Robust valid_lens decode: the reference declares int64 but JAX-without-x64
// materializes int32. valid_lens are always >= 1, so an int64-LE buffer viewed
// as int32 is [v0, 0, v1, 0, ...] -> zeros at odd slots discriminate layouts.
__device__ __forceinline__ int load_vlen(const int* vl32, int b) {
    bool is64 = (vl32[1] == 0) && (vl32[3] == 0);
    return is64 ? vl32[2 * b] : vl32[b];
}

// ---------------------------------------------------------------------------
// Tiled GEMM body: C[M,N] = A[M,K] @ B[K,N], row-major. M,N multiples of 64,
// K multiple of 16. 256 threads, each computes a 4x4 microtile of a 64x64 tile.
// ---------------------------------------------------------------------------
__device__ __forceinline__ void gemm_body(const float* __restrict__ A,
                                          const float* __restrict__ Bm,
                                          float* __restrict__ C,
                                          int M, int N, int K) {
    constexpr int BM = 64, BN = 64, BK = 16;
    __shared__ float As[BM][BK];   // [row][k]
    __shared__ float Bs[BK][BN];   // [k][col]

    const int m0 = blockIdx.y * BM;
    const int n0 = blockIdx.x * BN;
    const int tid = threadIdx.x;
    const int tx = tid & 15;       // 0..15 -> 4 cols each
    const int ty = tid >> 4;       // 0..15 -> 4 rows each

    float acc[4][4] = {};

    for (int k0 = 0; k0 < K; k0 += BK) {
        // Load A tile 64x16 (1024 elems / 256 threads = 4 each)
#pragma unroll
        for (int i = 0; i < 4; i++) {
            int idx = tid + i * 256;
            int r = idx >> 4, c = idx & 15;
            As[r][c] = A[(size_t)(m0 + r) * K + (k0 + c)];
        }
        // Load B tile 16x64 (coalesced along N)
#pragma unroll
        for (int i = 0; i < 4; i++) {
            int idx = tid + i * 256;
            int r = idx >> 6, c = idx & 63;
            Bs[r][c] = Bm[(size_t)(k0 + r) * N + (n0 + c)];
        }
        __syncthreads();

#pragma unroll
        for (int kk = 0; kk < BK; kk++) {
            float a0 = As[ty * 4 + 0][kk];
            float a1 = As[ty * 4 + 1][kk];
            float a2 = As[ty * 4 + 2][kk];
            float a3 = As[ty * 4 + 3][kk];
            float4 bv = *(const float4*)&Bs[kk][tx * 4];
            float b[4] = {bv.x, bv.y, bv.z, bv.w};
#pragma unroll
            for (int j = 0; j < 4; j++) {
                acc[0][j] = fmaf(a0, b[j], acc[0][j]);
                acc[1][j] = fmaf(a1, b[j], acc[1][j]);
                acc[2][j] = fmaf(a2, b[j], acc[2][j]);
                acc[3][j] = fmaf(a3, b[j], acc[3][j]);
            }
        }
        __syncthreads();
    }

#pragma unroll
    for (int i = 0; i < 4; i++) {
#pragma unroll
        for (int j = 0; j < 4; j++) {
            C[(size_t)(m0 + ty * 4 + i) * N + (n0 + tx * 4 + j)] = acc[i][j];
        }
    }
}

// q projection: [B*Q, QS] @ Wq[QS, H] -> g_qproj
__global__ void __launch_bounds__(256) gemm_qproj_kernel(const float* __restrict__ queries,
                                                         const float* __restrict__ Wq) {
    gemm_body(queries, Wq, g_qproj, BB * QQ, HH, QS);
}

// k projection: [B*K, KS] @ Wk[KS, H] -> g_kproj
__global__ void __launch_bounds__(256) gemm_kproj_kernel(const float* __restrict__ keys,
                                                         const float* __restrict__ Wk) {
    gemm_body(keys, Wk, g_kproj, BB * KK, HH, KSZ);
}

// AV: per batch, g_attn[b] [Q,K] @ values[b] [K,DV] -> out[b] [Q,DV]
__global__ void __launch_bounds__(256) gemm_av_kernel(const float* __restrict__ values,
                                                      float* __restrict__ out) {
    const int b = blockIdx.z;
    gemm_body(g_attn + (size_t)b * QQ * KK,
              values + (size_t)b * KK * DV,
              out + (size_t)b * QQ * DV,
              QQ, DV, KK);
}

// ---------------------------------------------------------------------------
// Fused scores + masked softmax.
// One CTA per (b, q). 8 warps; each warp owns k = wid, wid+8, ... (128 k's).
// Per k: lane holds 8 h-values (2x float4), tanh(q+k)*Wv, warp reduction.
// Then block softmax over K=1024 with mask (k >= valid_len -> -1e6).
// ---------------------------------------------------------------------------
__device__ __forceinline__ float tanh_fast(float x) {
    // tanh(x) = 1 - 2/(e^{2x}+1); accurate to ~1e-7 abs, saturates correctly.
    float t = __expf(2.0f * x);
    return 1.0f - __fdividef(2.0f, t + 1.0f);
}

__global__ void __launch_bounds__(256) scores_softmax_kernel(const float* __restrict__ Wv,
                                                             const int* __restrict__ valid_lens32) {
    const int b = blockIdx.y;
    const int q = blockIdx.x;
    const int tid = threadIdx.x;
    const int lane = tid & 31;
    const int wid = tid >> 5;

    __shared__ float s_scores[KK];
    __shared__ float s_red[8];

    // Register-resident q-row slice and Wv slice for this lane's 8 h-values
    const float4* qp = (const float4*)(g_qproj + ((size_t)(b * QQ + q)) * HH);
    const float4* wvp = (const float4*)Wv;
    const float4 q0 = qp[lane];
    const float4 q1 = qp[lane + 32];
    const float4 w0 = wvp[lane];
    const float4 w1 = wvp[lane + 32];

    const int vlen = load_vlen(valid_lens32, b);
    const float4* kbase = (const float4*)(g_kproj + (size_t)b * KK * HH);

    for (int k = wid; k < KK; k += 8) {
        float s = -1e6f;
        if (k < vlen) {
            const float4* kp = kbase + (size_t)k * (HH / 4);
            float4 k0 = kp[lane];
            float4 k1 = kp[lane + 32];
            float p;
            p = tanh_fast(q0.x + k0.x) * w0.x;
            p = fmaf(tanh_fast(q0.y + k0.y), w0.y, p);
            p = fmaf(tanh_fast(q0.z + k0.z), w0.z, p);
            p = fmaf(tanh_fast(q0.w + k0.w), w0.w, p);
            p = fmaf(tanh_fast(q1.x + k1.x), w1.x, p);
            p = fmaf(tanh_fast(q1.y + k1.y), w1.y, p);
            p = fmaf(tanh_fast(q1.z + k1.z), w1.z, p);
            p = fmaf(tanh_fast(q1.w + k1.w), w1.w, p);
#pragma unroll
            for (int off = 16; off; off >>= 1)
                p += __shfl_xor_sync(0xffffffffu, p, off);
            s = p;
        }
        if (lane == 0) s_scores[k] = s;
    }
    __syncthreads();

    // --- block max over 1024 scores ---
    float m = -3.4e38f;
#pragma unroll
    for (int i = 0; i < 4; i++) m = fmaxf(m, s_scores[tid + i * 256]);
#pragma unroll
    for (int off = 16; off; off >>= 1)
        m = fmaxf(m, __shfl_xor_sync(0xffffffffu, m, off));
    if (lane == 0) s_red[wid] = m;
    __syncthreads();
    float gmax = s_red[0];
#pragma unroll
    for (int i = 1; i < 8; i++) gmax = fmaxf(gmax, s_red[i]);
    __syncthreads();   // everyone done reading s_red before reuse

    // --- exp + block sum ---
    float e[4];
    float sum = 0.0f;
#pragma unroll
    for (int i = 0; i < 4; i++) {
        e[i] = __expf(s_scores[tid + i * 256] - gmax);
        sum += e[i];
    }
#pragma unroll
    for (int off = 16; off; off >>= 1)
        sum += __shfl_xor_sync(0xffffffffu, sum, off);
    if (lane == 0) s_red[wid] = sum;
    __syncthreads();
    float tot = s_red[0];
#pragma unroll
    for (int i = 1; i < 8; i++) tot += s_red[i];
    const float inv = __fdividef(1.0f, tot);

    float* ap = g_attn + ((size_t)(b * QQ + q)) * KK;
#pragma unroll
    for (int i = 0; i < 4; i++) ap[tid + i * 256] = e[i] * inv;
}

// ---------------------------------------------------------------------------
// Launch
// ---------------------------------------------------------------------------
extern "C" void kernel_launch(void* const* d_in, const int* in_sizes, int n_in,
                              void* d_out, int out_size) {
    const float* queries = (const float*)d_in[0];       // [B,Q,QS]
    const float* keys    = (const float*)d_in[1];       // [B,K,KS]
    const float* values  = (const float*)d_in[2];       // [B,K,DV]
    const int*   valid_lens = (const int*)d_in[3];      // [B] int32 or int64 (auto-detected)
    const float* Wq = (const float*)d_in[4];            // [QS,H]
    const float* Wk = (const float*)d_in[5];            // [KS,H]
    const float* Wv = (const float*)d_in[6];            // [H]
    float* out = (float*)d_out;                         // [B,Q,DV]

    (void)in_sizes; (void)n_in; (void)out_size;

    // Q projection: M=512, N=256 -> grid (4, 8)
    gemm_qproj_kernel<<<dim3(HH / 64, (BB * QQ) / 64), 256>>>(queries, Wq);
    // K projection: M=4096, N=256 -> grid (4, 64)
    gemm_kproj_kernel<<<dim3(HH / 64, (BB * KK) / 64), 256>>>(keys, Wk);
    // Scores + masked softmax: one CTA per (b, q)
    scores_softmax_kernel<<<dim3(QQ, BB), 256>>>(Wv, valid_lens);
    // AV: per batch 128x256 output, tiles (4, 2) per batch
    gemm_av_kernel<<<dim3(DV / 64, QQ / 64, BB), 256>>>(values, out);
}

// round 4
// speedup vs baseline: 1.5230x; 1.5230x over previous
#include <cuda_runtime.h>

// Problem shapes (fixed by the reference)
#define BB 4
#define QQ 128
#define KK 1024
#define HH 256
#define QS 256
#define KSZ 256
#define DV 256
#define SPLITS 8          // split-K factor for the AV GEMM

// Scratch (alloc-free rule: __device__ globals)
__device__ float g_qproj[BB * QQ * HH];                 // [B,Q,H]
__device__ float g_kproj[BB * KK * HH];                 // [B,K,H]
__device__ float g_attn [BB * QQ * KK];                 // [B,Q,K]
__device__ float g_avpart[BB * SPLITS * QQ * DV];       // [B,S,Q,DV]

// Robust valid_lens decode: reference says int64 but may materialize int32.
// valid_lens >= 1 always, so int64-LE viewed as int32 has zeros at odd slots.
__device__ __forceinline__ int load_vlen(const int* vl32, int b) {
    bool is64 = (vl32[1] == 0) && (vl32[3] == 0);
    return is64 ? vl32[2 * b] : vl32[b];
}

// ---------------------------------------------------------------------------
// Tiled GEMM body over a k-range: C[M,N] (+)= A[M,kb:ke] @ B[kb:ke,N].
// Row-major, 64x64 tile per CTA, 256 threads, 4x4 microtile each, BK=16.
// ---------------------------------------------------------------------------
__device__ __forceinline__ void gemm_body(const float* __restrict__ A,
                                          const float* __restrict__ Bm,
                                          float* __restrict__ C,
                                          int M, int N, int K,
                                          int kb, int ke) {
    constexpr int BM = 64, BN = 64, BK = 16;
    __shared__ float As[BM][BK + 1];   // +1 pad: kill 2-way LDS conflict
    __shared__ float Bs[BK][BN];

    const int m0 = blockIdx.y * BM;
    const int n0 = blockIdx.x * BN;
    const int tid = threadIdx.x;
    const int tx = tid & 15;
    const int ty = tid >> 4;

    float acc[4][4] = {};

    for (int k0 = kb; k0 < ke; k0 += BK) {
#pragma unroll
        for (int i = 0; i < 4; i++) {
            int idx = tid + i * 256;
            int r = idx >> 4, c = idx & 15;
            As[r][c] = A[(size_t)(m0 + r) * K + (k0 + c)];
        }
#pragma unroll
        for (int i = 0; i < 4; i++) {
            int idx = tid + i * 256;
            int r = idx >> 6, c = idx & 63;
            Bs[r][c] = Bm[(size_t)(k0 + r) * N + (n0 + c)];
        }
        __syncthreads();

#pragma unroll
        for (int kk = 0; kk < BK; kk++) {
            float a0 = As[ty * 4 + 0][kk];
            float a1 = As[ty * 4 + 1][kk];
            float a2 = As[ty * 4 + 2][kk];
            float a3 = As[ty * 4 + 3][kk];
            float4 bv = *(const float4*)&Bs[kk][tx * 4];
            float b[4] = {bv.x, bv.y, bv.z, bv.w};
#pragma unroll
            for (int j = 0; j < 4; j++) {
                acc[0][j] = fmaf(a0, b[j], acc[0][j]);
                acc[1][j] = fmaf(a1, b[j], acc[1][j]);
                acc[2][j] = fmaf(a2, b[j], acc[2][j]);
                acc[3][j] = fmaf(a3, b[j], acc[3][j]);
            }
        }
        __syncthreads();
    }

#pragma unroll
    for (int i = 0; i < 4; i++) {
#pragma unroll
        for (int j = 0; j < 4; j++) {
            C[(size_t)(m0 + ty * 4 + i) * N + (n0 + tx * 4 + j)] = acc[i][j];
        }
    }
}

// q projection: [B*Q, QS] @ Wq[QS, H] -> g_qproj   (grid: 4 x 8)
__global__ void __launch_bounds__(256) gemm_qproj_kernel(const float* __restrict__ queries,
                                                         const float* __restrict__ Wq) {
    gemm_body(queries, Wq, g_qproj, BB * QQ, HH, QS, 0, QS);
}

// k projection: [B*K, KS] @ Wk[KS, H] -> g_kproj   (grid: 4 x 64)
__global__ void __launch_bounds__(256) gemm_kproj_kernel(const float* __restrict__ keys,
                                                         const float* __restrict__ Wk) {
    gemm_body(keys, Wk, g_kproj, BB * KK, HH, KSZ, 0, KSZ);
}

// ---------------------------------------------------------------------------
// AV split-K: partial[b,s] = attn[b][:, kb:ke] @ values[b][kb:ke, :]
// grid (DV/64=4, QQ/64=2, BB*SPLITS=32) = 256 CTAs.
// Splits fully beyond valid_len have exactly-zero attn -> write zeros, exit.
// ---------------------------------------------------------------------------
__global__ void __launch_bounds__(256) gemm_av_split_kernel(const float* __restrict__ values,
                                                            const int* __restrict__ valid_lens32) {
    const int z = blockIdx.z;
    const int b = z / SPLITS;
    const int s = z % SPLITS;
    const int kb = s * (KK / SPLITS);
    const int ke = kb + (KK / SPLITS);

    float* Cp = g_avpart + (size_t)z * QQ * DV;

    const int vlen = load_vlen(valid_lens32, b);
    if (kb >= vlen) {
        // Entire split masked: attn row is exactly 0 there. Zero our tile.
        const int m0 = blockIdx.y * 64, n0 = blockIdx.x * 64;
        const int tid = threadIdx.x;
        const int tx = tid & 15, ty = tid >> 4;
#pragma unroll
        for (int i = 0; i < 4; i++) {
            float4 zv = {0.f, 0.f, 0.f, 0.f};
            *(float4*)&Cp[(size_t)(m0 + ty * 4 + i) * DV + (n0 + tx * 4)] = zv;
        }
        return;
    }

    gemm_body(g_attn + (size_t)b * QQ * KK,
              values + (size_t)b * KK * DV,
              Cp, QQ, DV, KK, kb, ke);
}

// Reduce partials: out[b][i] = sum_s partial[b][s][i]. float4-wide.
__global__ void __launch_bounds__(256) av_reduce_kernel(float* __restrict__ out) {
    const int idx = blockIdx.x * 256 + threadIdx.x;       // float4 index, total 32768
    const int per_b = QQ * DV / 4;                        // 8192 float4 per batch
    const int b = idx / per_b;
    const int i = idx % per_b;
    const float4* base = (const float4*)(g_avpart) + (size_t)b * SPLITS * per_b + i;
    float4 acc = base[0];
#pragma unroll
    for (int s = 1; s < SPLITS; s++) {
        float4 v = base[(size_t)s * per_b];
        acc.x += v.x; acc.y += v.y; acc.z += v.z; acc.w += v.w;
    }
    ((float4*)out)[idx] = acc;
}

// ---------------------------------------------------------------------------
// Fused scores + masked softmax. One CTA per (b,q); 8 warps; warp-per-k.
// ---------------------------------------------------------------------------
__device__ __forceinline__ float tanh_approx(float x) {
    float y;
    asm("tanh.approx.f32 %0, %1;" : "=f"(y) : "f"(x));
    return y;
}

__global__ void __launch_bounds__(256) scores_softmax_kernel(const float* __restrict__ Wv,
                                                             const int* __restrict__ valid_lens32) {
    const int b = blockIdx.y;
    const int q = blockIdx.x;
    const int tid = threadIdx.x;
    const int lane = tid & 31;
    const int wid = tid >> 5;

    __shared__ float s_scores[KK];
    __shared__ float s_red[8];

    const float4* qp = (const float4*)(g_qproj + ((size_t)(b * QQ + q)) * HH);
    const float4* wvp = (const float4*)Wv;
    const float4 q0 = qp[lane];
    const float4 q1 = qp[lane + 32];
    const float4 w0 = wvp[lane];
    const float4 w1 = wvp[lane + 32];

    const int vlen = load_vlen(valid_lens32, b);
    const float4* kbase = (const float4*)(g_kproj + (size_t)b * KK * HH);

    for (int k = wid; k < KK; k += 8) {
        float s = -1e6f;
        if (k < vlen) {
            const float4* kp = kbase + (size_t)k * (HH / 4);
            float4 k0 = kp[lane];
            float4 k1 = kp[lane + 32];
            float p;
            p = tanh_approx(q0.x + k0.x) * w0.x;
            p = fmaf(tanh_approx(q0.y + k0.y), w0.y, p);
            p = fmaf(tanh_approx(q0.z + k0.z), w0.z, p);
            p = fmaf(tanh_approx(q0.w + k0.w), w0.w, p);
            p = fmaf(tanh_approx(q1.x + k1.x), w1.x, p);
            p = fmaf(tanh_approx(q1.y + k1.y), w1.y, p);
            p = fmaf(tanh_approx(q1.z + k1.z), w1.z, p);
            p = fmaf(tanh_approx(q1.w + k1.w), w1.w, p);
#pragma unroll
            for (int off = 16; off; off >>= 1)
                p += __shfl_xor_sync(0xffffffffu, p, off);
            s = p;
        }
        if (lane == 0) s_scores[k] = s;
    }
    __syncthreads();

    // block max
    float m = -3.4e38f;
#pragma unroll
    for (int i = 0; i < 4; i++) m = fmaxf(m, s_scores[tid + i * 256]);
#pragma unroll
    for (int off = 16; off; off >>= 1)
        m = fmaxf(m, __shfl_xor_sync(0xffffffffu, m, off));
    if (lane == 0) s_red[wid] = m;
    __syncthreads();
    float gmax = s_red[0];
#pragma unroll
    for (int i = 1; i < 8; i++) gmax = fmaxf(gmax, s_red[i]);
    __syncthreads();

    // exp + block sum
    float e[4];
    float sum = 0.0f;
#pragma unroll
    for (int i = 0; i < 4; i++) {
        e[i] = __expf(s_scores[tid + i * 256] - gmax);
        sum += e[i];
    }
#pragma unroll
    for (int off = 16; off; off >>= 1)
        sum += __shfl_xor_sync(0xffffffffu, sum, off);
    if (lane == 0) s_red[wid] = sum;
    __syncthreads();
    float tot = s_red[0];
#pragma unroll
    for (int i = 1; i < 8; i++) tot += s_red[i];
    const float inv = __fdividef(1.0f, tot);

    float* ap = g_attn + ((size_t)(b * QQ + q)) * KK;
#pragma unroll
    for (int i = 0; i < 4; i++) ap[tid + i * 256] = e[i] * inv;
}

// ---------------------------------------------------------------------------
// Launch
// ---------------------------------------------------------------------------
extern "C" void kernel_launch(void* const* d_in, const int* in_sizes, int n_in,
                              void* d_out, int out_size) {
    const float* queries = (const float*)d_in[0];
    const float* keys    = (const float*)d_in[1];
    const float* values  = (const float*)d_in[2];
    const int*   valid_lens = (const int*)d_in[3];
    const float* Wq = (const float*)d_in[4];
    const float* Wk = (const float*)d_in[5];
    const float* Wv = (const float*)d_in[6];
    float* out = (float*)d_out;

    (void)in_sizes; (void)n_in; (void)out_size;

    gemm_qproj_kernel<<<dim3(HH / 64, (BB * QQ) / 64), 256>>>(queries, Wq);
    gemm_kproj_kernel<<<dim3(HH / 64, (BB * KK) / 64), 256>>>(keys, Wk);
    scores_softmax_kernel<<<dim3(QQ, BB), 256>>>(Wv, valid_lens);
    gemm_av_split_kernel<<<dim3(DV / 64, QQ / 64, BB * SPLITS), 256>>>(values, valid_lens);
    av_reduce_kernel<<<(BB * QQ * DV / 4) / 256, 256>>>(out);
}

// round 6
// speedup vs baseline: 1.8670x; 1.2259x over previous
#include <cuda_runtime.h>

// Problem shapes (fixed by the reference)
#define BB 4
#define QQ 128
#define KK 1024
#define HH 256
#define QS 256
#define KSZ 256
#define DV 256
#define SPLITS 16         // split-K factor for the AV GEMM
#define QT 16             // q-tile in scores kernel
#define KC 128            // k-chunk in scores kernel

// Scratch (alloc-free rule: __device__ globals)
__device__ float g_qproj[BB * QQ * HH];                 // [B,Q,H]
__device__ float g_kproj[BB * KK * HH];                 // [B,K,H]
__device__ float g_attn [BB * QQ * KK];                 // [B,Q,K] raw scores -> probs (in place)
__device__ float g_avpart[BB * SPLITS * QQ * DV];       // [B,S,Q,DV]

// Robust valid_lens decode: reference says int64 but may materialize int32.
// valid_lens >= 1 always, so int64-LE viewed as int32 has zeros at odd slots.
__device__ __forceinline__ int load_vlen(const int* vl32, int b) {
    bool is64 = (vl32[1] == 0) && (vl32[3] == 0);
    return is64 ? vl32[2 * b] : vl32[b];
}

__device__ __forceinline__ float tanh_approx(float x) {
    float y;
    asm("tanh.approx.f32 %0, %1;" : "=f"(y) : "f"(x));
    return y;
}

// ---------------------------------------------------------------------------
// Tiled GEMM body over a k-range with register-prefetch double buffering.
// C tile (64x64) at (m0,n0): C = A[m0:m0+64, kb:ke] @ B[kb:ke, n0:n0+64].
// 256 threads, 4x4 microtile each, BK=16.
// ---------------------------------------------------------------------------
__device__ __forceinline__ void gemm_body(const float* __restrict__ A,
                                          const float* __restrict__ Bm,
                                          float* __restrict__ C,
                                          int N, int K, int kb, int ke,
                                          int m0, int n0) {
    constexpr int BK = 16;
    __shared__ float As[64][BK + 1];
    __shared__ float Bs[BK][64];

    const int tid = threadIdx.x;
    const int tx = tid & 15;
    const int ty = tid >> 4;

    float acc[4][4] = {};
    float a_reg[4], b_reg[4];

    // prefetch first tiles
#pragma unroll
    for (int i = 0; i < 4; i++) {
        int idx = tid + i * 256;
        a_reg[i] = A[(size_t)(m0 + (idx >> 4)) * K + (kb + (idx & 15))];
        b_reg[i] = Bm[(size_t)(kb + (idx >> 6)) * N + (n0 + (idx & 63))];
    }

    for (int k0 = kb; k0 < ke; k0 += BK) {
#pragma unroll
        for (int i = 0; i < 4; i++) {
            int idx = tid + i * 256;
            As[idx >> 4][idx & 15] = a_reg[i];
            Bs[idx >> 6][idx & 63] = b_reg[i];
        }
        __syncthreads();

        if (k0 + BK < ke) {  // prefetch next tiles (overlaps compute below)
#pragma unroll
            for (int i = 0; i < 4; i++) {
                int idx = tid + i * 256;
                a_reg[i] = A[(size_t)(m0 + (idx >> 4)) * K + (k0 + BK + (idx & 15))];
                b_reg[i] = Bm[(size_t)(k0 + BK + (idx >> 6)) * N + (n0 + (idx & 63))];
            }
        }

#pragma unroll
        for (int kk = 0; kk < BK; kk++) {
            float a0 = As[ty * 4 + 0][kk];
            float a1 = As[ty * 4 + 1][kk];
            float a2 = As[ty * 4 + 2][kk];
            float a3 = As[ty * 4 + 3][kk];
            float4 bv = *(const float4*)&Bs[kk][tx * 4];
            float b[4] = {bv.x, bv.y, bv.z, bv.w};
#pragma unroll
            for (int j = 0; j < 4; j++) {
                acc[0][j] = fmaf(a0, b[j], acc[0][j]);
                acc[1][j] = fmaf(a1, b[j], acc[1][j]);
                acc[2][j] = fmaf(a2, b[j], acc[2][j]);
                acc[3][j] = fmaf(a3, b[j], acc[3][j]);
            }
        }
        __syncthreads();
    }

#pragma unroll
    for (int i = 0; i < 4; i++) {
#pragma unroll
        for (int j = 0; j < 4; j++) {
            C[(size_t)(m0 + ty * 4 + i) * N + (n0 + tx * 4 + j)] = acc[i][j];
        }
    }
}

// ---------------------------------------------------------------------------
// Merged projections: blockIdx.y < 8 -> q-proj tiles, else k-proj tiles.
// grid (HH/64=4, 8 + 64 = 72)
// ---------------------------------------------------------------------------
__global__ void __launch_bounds__(256) gemm_proj_kernel(const float* __restrict__ queries,
                                                        const float* __restrict__ keys,
                                                        const float* __restrict__ Wq,
                                                        const float* __restrict__ Wk) {
    const int by = blockIdx.y;
    const int n0 = blockIdx.x * 64;
    if (by < (BB * QQ) / 64) {
        gemm_body(queries, Wq, g_qproj, HH, QS, 0, QS, by * 64, n0);
    } else {
        gemm_body(keys, Wk, g_kproj, HH, KSZ, 0, KSZ, (by - (BB * QQ) / 64) * 64, n0);
    }
}

// ---------------------------------------------------------------------------
// Q-tiled scores: CTA = (kc, qt, b). Loads q-tile (16x256) into smem once,
// each warp owns 16 contiguous k's; per k loads the k-vector once into regs
// and reuses it across all 16 q's. Skips k >= valid_len entirely.
// Raw scores written to g_attn (masked region left stale; softmax masks by index).
// grid (8, 8, 4) = 256 CTAs.
// ---------------------------------------------------------------------------
__global__ void __launch_bounds__(256) scores_kernel(const float* __restrict__ Wv,
                                                     const int* __restrict__ valid_lens32) {
    const int b = blockIdx.z;
    const int qt = blockIdx.y;
    const int kc = blockIdx.x;
    const int tid = threadIdx.x;
    const int lane = tid & 31;
    const int wid = tid >> 5;

    __shared__ float s_q[QT][HH];

    // stage q tile (4096 floats = 1024 float4; 4 per thread)
    const float4* qbase = (const float4*)(g_qproj + ((size_t)(b * QQ + qt * QT)) * HH);
#pragma unroll
    for (int i = 0; i < 4; i++) {
        int idx = tid + i * 256;
        ((float4*)&s_q[0][0])[idx] = qbase[idx];
    }
    __syncthreads();

    const float4* wv4 = (const float4*)Wv;
    const float4 w0 = wv4[lane];
    const float4 w1 = wv4[lane + 32];

    const int vlen = load_vlen(valid_lens32, b);
    const int kstart = kc * KC + wid * 16;
    float* srow = g_attn + ((size_t)(b * QQ + qt * QT)) * KK;

    for (int j = 0; j < 16; j++) {
        const int k = kstart + j;
        if (k >= vlen) break;   // contiguous ks per warp -> safe to break
        const float4* kp = (const float4*)(g_kproj + ((size_t)(b * KK + k)) * HH);
        const float4 k0 = kp[lane];
        const float4 k1 = kp[lane + 32];
#pragma unroll
        for (int q = 0; q < QT; q++) {
            float4 qa = *(const float4*)&s_q[q][lane * 4];
            float4 qb = *(const float4*)&s_q[q][128 + lane * 4];
            float p;
            p = tanh_approx(qa.x + k0.x) * w0.x;
            p = fmaf(tanh_approx(qa.y + k0.y), w0.y, p);
            p = fmaf(tanh_approx(qa.z + k0.z), w0.z, p);
            p = fmaf(tanh_approx(qa.w + k0.w), w0.w, p);
            p = fmaf(tanh_approx(qb.x + k1.x), w1.x, p);
            p = fmaf(tanh_approx(qb.y + k1.y), w1.y, p);
            p = fmaf(tanh_approx(qb.z + k1.z), w1.z, p);
            p = fmaf(tanh_approx(qb.w + k1.w), w1.w, p);
#pragma unroll
            for (int off = 16; off; off >>= 1)
                p += __shfl_xor_sync(0xffffffffu, p, off);
            if (lane == 0) srow[(size_t)q * KK + k] = p;
        }
    }
}

// ---------------------------------------------------------------------------
// Masked softmax over each row of g_attn, in place. grid (QQ, BB) = 512 CTAs.
// ---------------------------------------------------------------------------
__global__ void __launch_bounds__(256) softmax_kernel(const int* __restrict__ valid_lens32) {
    const int b = blockIdx.y;
    const int q = blockIdx.x;
    const int tid = threadIdx.x;
    const int lane = tid & 31;
    const int wid = tid >> 5;

    __shared__ float s_red[8];

    const int vlen = load_vlen(valid_lens32, b);
    float* row = g_attn + ((size_t)(b * QQ + q)) * KK;

    float v[4];
#pragma unroll
    for (int i = 0; i < 4; i++) {
        int k = tid + i * 256;
        float s = row[k];
        v[i] = (k < vlen) ? s : -1e6f;
    }

    // block max
    float m = fmaxf(fmaxf(v[0], v[1]), fmaxf(v[2], v[3]));
#pragma unroll
    for (int off = 16; off; off >>= 1)
        m = fmaxf(m, __shfl_xor_sync(0xffffffffu, m, off));
    if (lane == 0) s_red[wid] = m;
    __syncthreads();
    float gmax = s_red[0];
#pragma unroll
    for (int i = 1; i < 8; i++) gmax = fmaxf(gmax, s_red[i]);
    __syncthreads();

    // exp + block sum
    float sum = 0.0f;
#pragma unroll
    for (int i = 0; i < 4; i++) {
        v[i] = __expf(v[i] - gmax);
        sum += v[i];
    }
#pragma unroll
    for (int off = 16; off; off >>= 1)
        sum += __shfl_xor_sync(0xffffffffu, sum, off);
    if (lane == 0) s_red[wid] = sum;
    __syncthreads();
    float tot = s_red[0];
#pragma unroll
    for (int i = 1; i < 8; i++) tot += s_red[i];
    const float inv = __fdividef(1.0f, tot);

#pragma unroll
    for (int i = 0; i < 4; i++) row[tid + i * 256] = v[i] * inv;
}

// ---------------------------------------------------------------------------
// AV split-K: partial[b,s] = attn[b][:, kb:ke] @ values[b][kb:ke, :]
// grid (DV/64=4, QQ/64=2, BB*SPLITS=64) = 512 CTAs.
// ---------------------------------------------------------------------------
__global__ void __launch_bounds__(256) gemm_av_split_kernel(const float* __restrict__ values,
                                                            const int* __restrict__ valid_lens32) {
    const int z = blockIdx.z;
    const int b = z / SPLITS;
    const int s = z % SPLITS;
    const int kb = s * (KK / SPLITS);
    const int ke = kb + (KK / SPLITS);

    float* Cp = g_avpart + (size_t)z * QQ * DV;
    const int m0 = blockIdx.y * 64, n0 = blockIdx.x * 64;

    const int vlen = load_vlen(valid_lens32, b);
    if (kb >= vlen) {
        const int tid = threadIdx.x;
        const int tx = tid & 15, ty = tid >> 4;
        float4 zv = {0.f, 0.f, 0.f, 0.f};
#pragma unroll
        for (int i = 0; i < 4; i++)
            *(float4*)&Cp[(size_t)(m0 + ty * 4 + i) * DV + (n0 + tx * 4)] = zv;
        return;
    }

    gemm_body(g_attn + (size_t)b * QQ * KK,
              values + (size_t)b * KK * DV,
              Cp, DV, KK, kb, ke, m0, n0);
}

// Reduce partials: out[b][i] = sum_s partial[b][s][i]. float4-wide.
__global__ void __launch_bounds__(256) av_reduce_kernel(float* __restrict__ out) {
    const int idx = blockIdx.x * 256 + threadIdx.x;       // float4 index, 32768 total
    const int per_b = QQ * DV / 4;                        // 8192 float4 per batch
    const int b = idx / per_b;
    const int i = idx % per_b;
    const float4* base = (const float4*)(g_avpart) + (size_t)b * SPLITS * per_b + i;
    float4 acc = base[0];
#pragma unroll
    for (int s = 1; s < SPLITS; s++) {
        float4 v = base[(size_t)s * per_b];
        acc.x += v.x; acc.y += v.y; acc.z += v.z; acc.w += v.w;
    }
    ((float4*)out)[idx] = acc;
}

// ---------------------------------------------------------------------------
// Launch
// ---------------------------------------------------------------------------
extern "C" void kernel_launch(void* const* d_in, const int* in_sizes, int n_in,
                              void* d_out, int out_size) {
    const float* queries = (const float*)d_in[0];
    const float* keys    = (const float*)d_in[1];
    const float* values  = (const float*)d_in[2];
    const int*   valid_lens = (const int*)d_in[3];
    const float* Wq = (const float*)d_in[4];
    const float* Wk = (const float*)d_in[5];
    const float* Wv = (const float*)d_in[6];
    float* out = (float*)d_out;

    (void)in_sizes; (void)n_in; (void)out_size;

    gemm_proj_kernel<<<dim3(HH / 64, (BB * QQ) / 64 + (BB * KK) / 64), 256>>>(queries, keys, Wq, Wk);
    scores_kernel<<<dim3(KK / KC, QQ / QT, BB), 256>>>(Wv, valid_lens);
    softmax_kernel<<<dim3(QQ, BB), 256>>>(valid_lens);
    gemm_av_split_kernel<<<dim3(DV / 64, QQ / 64, BB * SPLITS), 256>>>(values, valid_lens);
    av_reduce_kernel<<<(BB * QQ * DV / 4) / 256, 256>>>(out);
}

// round 9
// speedup vs baseline: 1.9212x; 1.0290x over previous
#include <cuda_runtime.h>

// Problem shapes (fixed by the reference)
#define BB 4
#define QQ 128
#define KK 1024
#define HH 256
#define QS 256
#define KSZ 256
#define DV 256
#define SPLITS 16         // split-K factor for the AV GEMM
#define QTILE 32          // q's per scores CTA (lane = q)
#define KT 8              // k's per warp in scores kernel
#define KCHUNK 64         // k's per scores CTA (8 warps x KT)
#define OPAD 12           // transpose-buffer row stride (multiple of 4 -> aligned LDS.128)

// Scratch (alloc-free rule: __device__ globals)
__device__ float g_qproj[BB * QQ * HH];                 // [B,Q,H]
__device__ float g_kproj[BB * KK * HH];                 // [B,K,H]
__device__ float g_attn [BB * QQ * KK];                 // [B,Q,K] raw scores -> probs (in place)
__device__ float g_avpart[BB * SPLITS * QQ * DV];       // [B,S,Q,DV]

// Robust valid_lens decode: reference says int64 but may materialize int32.
// valid_lens >= 1 always, so int64-LE viewed as int32 has zeros at odd slots.
__device__ __forceinline__ int load_vlen(const int* vl32, int b) {
    bool is64 = (vl32[1] == 0) && (vl32[3] == 0);
    return is64 ? vl32[2 * b] : vl32[b];
}

__device__ __forceinline__ float tanh_approx(float x) {
    float y;
    asm("tanh.approx.f32 %0, %1;" : "=f"(y) : "f"(x));
    return y;
}

// ---------------------------------------------------------------------------
// Tiled GEMM body over a k-range with register-prefetch double buffering.
// C tile (64x64) at (m0,n0): C = A[m0:m0+64, kb:ke] @ B[kb:ke, n0:n0+64].
// 256 threads, 4x4 microtile each, BK=16.
// ---------------------------------------------------------------------------
__device__ __forceinline__ void gemm_body(const float* __restrict__ A,
                                          const float* __restrict__ Bm,
                                          float* __restrict__ C,
                                          int N, int K, int kb, int ke,
                                          int m0, int n0) {
    constexpr int BK = 16;
    __shared__ float As[64][BK + 1];
    __shared__ float Bs[BK][64];

    const int tid = threadIdx.x;
    const int tx = tid & 15;
    const int ty = tid >> 4;

    float acc[4][4] = {};
    float a_reg[4], b_reg[4];

#pragma unroll
    for (int i = 0; i < 4; i++) {
        int idx = tid + i * 256;
        a_reg[i] = A[(size_t)(m0 + (idx >> 4)) * K + (kb + (idx & 15))];
        b_reg[i] = Bm[(size_t)(kb + (idx >> 6)) * N + (n0 + (idx & 63))];
    }

    for (int k0 = kb; k0 < ke; k0 += BK) {
#pragma unroll
        for (int i = 0; i < 4; i++) {
            int idx = tid + i * 256;
            As[idx >> 4][idx & 15] = a_reg[i];
            Bs[idx >> 6][idx & 63] = b_reg[i];
        }
        __syncthreads();

        if (k0 + BK < ke) {
#pragma unroll
            for (int i = 0; i < 4; i++) {
                int idx = tid + i * 256;
                a_reg[i] = A[(size_t)(m0 + (idx >> 4)) * K + (k0 + BK + (idx & 15))];
                b_reg[i] = Bm[(size_t)(k0 + BK + (idx >> 6)) * N + (n0 + (idx & 63))];
            }
        }

#pragma unroll
        for (int kk = 0; kk < BK; kk++) {
            float a0 = As[ty * 4 + 0][kk];
            float a1 = As[ty * 4 + 1][kk];
            float a2 = As[ty * 4 + 2][kk];
            float a3 = As[ty * 4 + 3][kk];
            float4 bv = *(const float4*)&Bs[kk][tx * 4];
            float b[4] = {bv.x, bv.y, bv.z, bv.w};
#pragma unroll
            for (int j = 0; j < 4; j++) {
                acc[0][j] = fmaf(a0, b[j], acc[0][j]);
                acc[1][j] = fmaf(a1, b[j], acc[1][j]);
                acc[2][j] = fmaf(a2, b[j], acc[2][j]);
                acc[3][j] = fmaf(a3, b[j], acc[3][j]);
            }
        }
        __syncthreads();
    }

#pragma unroll
    for (int i = 0; i < 4; i++) {
#pragma unroll
        for (int j = 0; j < 4; j++) {
            C[(size_t)(m0 + ty * 4 + i) * N + (n0 + tx * 4 + j)] = acc[i][j];
        }
    }
}

// Merged projections: blockIdx.y < 8 -> q-proj tiles, else k-proj tiles.
__global__ void __launch_bounds__(256) gemm_proj_kernel(const float* __restrict__ queries,
                                                        const float* __restrict__ keys,
                                                        const float* __restrict__ Wq,
                                                        const float* __restrict__ Wk) {
    const int by = blockIdx.y;
    const int n0 = blockIdx.x * 64;
    if (by < (BB * QQ) / 64) {
        gemm_body(queries, Wq, g_qproj, HH, QS, 0, QS, by * 64, n0);
    } else {
        gemm_body(keys, Wk, g_kproj, HH, KSZ, 0, KSZ, (by - (BB * QQ) / 64) * 64, n0);
    }
}

// ---------------------------------------------------------------------------
// Scores, lane-per-q layout (NO cross-lane reduction).
// CTA = (kc, qt, b): 32 q's staged in smem (pad 260 -> conflict-free LDS.128),
// 8 warps x 8 k's each; warp stages its k-rows in smem once; h-outer/k-inner
// loop with 8 independent accumulators per lane. Output transposed via smem
// (row stride OPAD=12 keeps float4 reads 16B-aligned) for coalesced STG.
// grid (16, 4, 4) = 256 CTAs. Dynamic smem ~107 KB.
// ---------------------------------------------------------------------------
extern __shared__ float s_dyn[];

__global__ void __launch_bounds__(256) scores_kernel(const float* __restrict__ Wv,
                                                     const int* __restrict__ valid_lens32) {
    const int b = blockIdx.z;
    const int qt = blockIdx.y;
    const int kc = blockIdx.x;
    const int tid = threadIdx.x;
    const int lane = tid & 31;
    const int wid = tid >> 5;

    // smem carve-up (floats): s_q[32][260] | s_w[256] | s_k[8][KT][256] | s_out[8][32][OPAD]
    float* s_q = s_dyn;                              // 32*260 = 8320
    float* s_w = s_q + QTILE * 260;                  // 256
    float* s_k = s_w + 256;                          // 8*KT*256 = 16384
    float* s_out = s_k + 8 * KT * 256;               // 8*32*12 = 3072

    // stage q tile: 32 rows x 256 = 2048 float4, 8 per thread
    const float4* qbase = (const float4*)(g_qproj + ((size_t)(b * QQ + qt * QTILE)) * HH);
#pragma unroll
    for (int i = 0; i < 8; i++) {
        int idx = tid + i * 256;
        int q = idx >> 6, h4 = idx & 63;
        *(float4*)&s_q[q * 260 + h4 * 4] = qbase[idx];
    }
    // stage Wv
    if (tid < 64) ((float4*)s_w)[tid] = ((const float4*)Wv)[tid];

    const int vlen = load_vlen(valid_lens32, b);
    const int k0 = kc * KCHUNK + wid * KT;
    const bool active = (k0 < vlen);

    // stage this warp's KT k-rows: KT*64 = 512 float4, 16 per lane
    if (active) {
        const float4* kb4 = (const float4*)(g_kproj + ((size_t)(b * KK + k0)) * HH);
        float* sk = s_k + wid * (KT * 256);
#pragma unroll
        for (int i = 0; i < 16; i++) {
            int idx = lane + i * 32;
            *(float4*)&sk[idx * 4] = kb4[idx];
        }
    }
    __syncthreads();

    if (!active) return;

    const float* sqrow = s_q + lane * 260;
    const float* sk = s_k + wid * (KT * 256);

    float acc[KT] = {};
#pragma unroll 2
    for (int h4 = 0; h4 < 64; h4++) {
        float4 qv = *(const float4*)&sqrow[h4 * 4];
        float4 wv = *(const float4*)&s_w[h4 * 4];
#pragma unroll
        for (int j = 0; j < KT; j++) {
            float4 kv = *(const float4*)&sk[j * 256 + h4 * 4];
            float a = acc[j];
            a = fmaf(tanh_approx(qv.x + kv.x), wv.x, a);
            a = fmaf(tanh_approx(qv.y + kv.y), wv.y, a);
            a = fmaf(tanh_approx(qv.z + kv.z), wv.z, a);
            a = fmaf(tanh_approx(qv.w + kv.w), wv.w, a);
            acc[j] = a;
        }
    }

    // transpose in smem: lane (=q) writes its KT scores as a row
    float* so = s_out + wid * (QTILE * OPAD);
#pragma unroll
    for (int j = 0; j < KT; j++) so[lane * OPAD + j] = acc[j];
    __syncwarp();

    // coalesced store: 32 q x 8 k = 64 float4; 2 per lane (aligned: OPAD % 4 == 0)
    float* srow = g_attn + ((size_t)(b * QQ + qt * QTILE)) * KK + k0;
#pragma unroll
    for (int i = 0; i < 2; i++) {
        int q = (lane >> 1) + i * 16;
        int p = (lane & 1) * 4;
        float4 v = *(const float4*)&so[q * OPAD + p];
        *(float4*)&srow[(size_t)q * KK + p] = v;
    }
}

// ---------------------------------------------------------------------------
// Masked softmax over each row of g_attn, in place. grid (QQ, BB) = 512 CTAs.
// ---------------------------------------------------------------------------
__global__ void __launch_bounds__(256) softmax_kernel(const int* __restrict__ valid_lens32) {
    const int b = blockIdx.y;
    const int q = blockIdx.x;
    const int tid = threadIdx.x;
    const int lane = tid & 31;
    const int wid = tid >> 5;

    __shared__ float s_red[8];

    const int vlen = load_vlen(valid_lens32, b);
    float* row = g_attn + ((size_t)(b * QQ + q)) * KK;

    float v[4];
#pragma unroll
    for (int i = 0; i < 4; i++) {
        int k = tid + i * 256;
        float s = row[k];
        v[i] = (k < vlen) ? s : -1e6f;
    }

    float m = fmaxf(fmaxf(v[0], v[1]), fmaxf(v[2], v[3]));
#pragma unroll
    for (int off = 16; off; off >>= 1)
        m = fmaxf(m, __shfl_xor_sync(0xffffffffu, m, off));
    if (lane == 0) s_red[wid] = m;
    __syncthreads();
    float gmax = s_red[0];
#pragma unroll
    for (int i = 1; i < 8; i++) gmax = fmaxf(gmax, s_red[i]);
    __syncthreads();

    float sum = 0.0f;
#pragma unroll
    for (int i = 0; i < 4; i++) {
        v[i] = __expf(v[i] - gmax);
        sum += v[i];
    }
#pragma unroll
    for (int off = 16; off; off >>= 1)
        sum += __shfl_xor_sync(0xffffffffu, sum, off);
    if (lane == 0) s_red[wid] = sum;
    __syncthreads();
    float tot = s_red[0];
#pragma unroll
    for (int i = 1; i < 8; i++) tot += s_red[i];
    const float inv = __fdividef(1.0f, tot);

#pragma unroll
    for (int i = 0; i < 4; i++) row[tid + i * 256] = v[i] * inv;
}

// ---------------------------------------------------------------------------
// AV split-K + reduce
// ---------------------------------------------------------------------------
__global__ void __launch_bounds__(256) gemm_av_split_kernel(const float* __restrict__ values,
                                                            const int* __restrict__ valid_lens32) {
    const int z = blockIdx.z;
    const int b = z / SPLITS;
    const int s = z % SPLITS;
    const int kb = s * (KK / SPLITS);
    const int ke = kb + (KK / SPLITS);

    float* Cp = g_avpart + (size_t)z * QQ * DV;
    const int m0 = blockIdx.y * 64, n0 = blockIdx.x * 64;

    const int vlen = load_vlen(valid_lens32, b);
    if (kb >= vlen) {
        const int tid = threadIdx.x;
        const int tx = tid & 15, ty = tid >> 4;
        float4 zv = {0.f, 0.f, 0.f, 0.f};
#pragma unroll
        for (int i = 0; i < 4; i++)
            *(float4*)&Cp[(size_t)(m0 + ty * 4 + i) * DV + (n0 + tx * 4)] = zv;
        return;
    }

    gemm_body(g_attn + (size_t)b * QQ * KK,
              values + (size_t)b * KK * DV,
              Cp, DV, KK, kb, ke, m0, n0);
}

__global__ void __launch_bounds__(256) av_reduce_kernel(float* __restrict__ out) {
    const int idx = blockIdx.x * 256 + threadIdx.x;
    const int per_b = QQ * DV / 4;
    const int b = idx / per_b;
    const int i = idx % per_b;
    const float4* base = (const float4*)(g_avpart) + (size_t)b * SPLITS * per_b + i;
    float4 acc = base[0];
#pragma unroll
    for (int s = 1; s < SPLITS; s++) {
        float4 v = base[(size_t)s * per_b];
        acc.x += v.x; acc.y += v.y; acc.z += v.z; acc.w += v.w;
    }
    ((float4*)out)[idx] = acc;
}

// ---------------------------------------------------------------------------
// Launch
// ---------------------------------------------------------------------------
extern "C" void kernel_launch(void* const* d_in, const int* in_sizes, int n_in,
                              void* d_out, int out_size) {
    const float* queries = (const float*)d_in[0];
    const float* keys    = (const float*)d_in[1];
    const float* values  = (const float*)d_in[2];
    const int*   valid_lens = (const int*)d_in[3];
    const float* Wq = (const float*)d_in[4];
    const float* Wk = (const float*)d_in[5];
    const float* Wv = (const float*)d_in[6];
    float* out = (float*)d_out;

    (void)in_sizes; (void)n_in; (void)out_size;

    const int smem_bytes = (QTILE * 260 + 256 + 8 * KT * 256 + 8 * QTILE * OPAD) * 4;
    cudaFuncSetAttribute(scores_kernel, cudaFuncAttributeMaxDynamicSharedMemorySize, smem_bytes);

    gemm_proj_kernel<<<dim3(HH / 64, (BB * QQ) / 64 + (BB * KK) / 64), 256>>>(queries, keys, Wq, Wk);
    scores_kernel<<<dim3(KK / KCHUNK, QQ / QTILE, BB), 256, smem_bytes>>>(Wv, valid_lens);
    softmax_kernel<<<dim3(QQ, BB), 256>>>(valid_lens);
    gemm_av_split_kernel<<<dim3(DV / 64, QQ / 64, BB * SPLITS), 256>>>(values, valid_lens);
    av_reduce_kernel<<<(BB * QQ * DV / 4) / 256, 256>>>(out);
}

// round 10
// speedup vs baseline: 1.9844x; 1.0329x over previous
#include <cuda_runtime.h>

// Problem shapes (fixed by the reference)
#define BB 4
#define QQ 128
#define KK 1024
#define HH 256
#define QS 256
#define KSZ 256
#define DV 256
#define SPLITS 16         // flash split-K factor (strided k assignment)
#define QTILE 32          // q's per flash CTA (lane = q)
#define KPC 64            // k's per flash CTA (= KK/SPLITS), 8 warps x 8
#define PPAD 68           // s_p row stride (q-major), multiple of 4

// Scratch (alloc-free rule: __device__ globals)
__device__ float g_qproj[BB * QQ * HH];                 // [B,Q,H]
__device__ float g_kproj[BB * KK * HH];                 // [B,K,H]
__device__ float g_Opart[SPLITS * BB * QQ * DV];        // per-split partial outputs
__device__ float g_mpart[SPLITS * BB * QQ];             // per-split row max
__device__ float g_Spart[SPLITS * BB * QQ];             // per-split exp-sum

// Robust valid_lens decode: reference says int64 but may materialize int32.
// valid_lens >= 1 always, so int64-LE viewed as int32 has zeros at odd slots.
__device__ __forceinline__ int load_vlen(const int* vl32, int b) {
    bool is64 = (vl32[1] == 0) && (vl32[3] == 0);
    return is64 ? vl32[2 * b] : vl32[b];
}

__device__ __forceinline__ float tanh_approx(float x) {
    float y;
    asm("tanh.approx.f32 %0, %1;" : "=f"(y) : "f"(x));
    return y;
}

// ---------------------------------------------------------------------------
// Tiled GEMM body (projections): C tile (64x64) at (m0,n0),
// C = A[m0:+64, 0:K] @ B[0:K, n0:+64]. 256 threads, 4x4 micro, BK=16,
// register-prefetch double buffering.
// ---------------------------------------------------------------------------
__device__ __forceinline__ void gemm_body(const float* __restrict__ A,
                                          const float* __restrict__ Bm,
                                          float* __restrict__ C,
                                          int N, int K, int m0, int n0) {
    constexpr int BK = 16;
    __shared__ float As[64][BK + 1];
    __shared__ float Bs[BK][64];

    const int tid = threadIdx.x;
    const int tx = tid & 15;
    const int ty = tid >> 4;

    float acc[4][4] = {};
    float a_reg[4], b_reg[4];

#pragma unroll
    for (int i = 0; i < 4; i++) {
        int idx = tid + i * 256;
        a_reg[i] = A[(size_t)(m0 + (idx >> 4)) * K + (idx & 15)];
        b_reg[i] = Bm[(size_t)(idx >> 6) * N + (n0 + (idx & 63))];
    }

    for (int k0 = 0; k0 < K; k0 += BK) {
#pragma unroll
        for (int i = 0; i < 4; i++) {
            int idx = tid + i * 256;
            As[idx >> 4][idx & 15] = a_reg[i];
            Bs[idx >> 6][idx & 63] = b_reg[i];
        }
        __syncthreads();

        if (k0 + BK < K) {
#pragma unroll
            for (int i = 0; i < 4; i++) {
                int idx = tid + i * 256;
                a_reg[i] = A[(size_t)(m0 + (idx >> 4)) * K + (k0 + BK + (idx & 15))];
                b_reg[i] = Bm[(size_t)(k0 + BK + (idx >> 6)) * N + (n0 + (idx & 63))];
            }
        }

#pragma unroll
        for (int kk = 0; kk < BK; kk++) {
            float a0 = As[ty * 4 + 0][kk];
            float a1 = As[ty * 4 + 1][kk];
            float a2 = As[ty * 4 + 2][kk];
            float a3 = As[ty * 4 + 3][kk];
            float4 bv = *(const float4*)&Bs[kk][tx * 4];
            float b[4] = {bv.x, bv.y, bv.z, bv.w};
#pragma unroll
            for (int j = 0; j < 4; j++) {
                acc[0][j] = fmaf(a0, b[j], acc[0][j]);
                acc[1][j] = fmaf(a1, b[j], acc[1][j]);
                acc[2][j] = fmaf(a2, b[j], acc[2][j]);
                acc[3][j] = fmaf(a3, b[j], acc[3][j]);
            }
        }
        __syncthreads();
    }

#pragma unroll
    for (int i = 0; i < 4; i++) {
#pragma unroll
        for (int j = 0; j < 4; j++) {
            C[(size_t)(m0 + ty * 4 + i) * N + (n0 + tx * 4 + j)] = acc[i][j];
        }
    }
}

// Merged projections: blockIdx.y < 8 -> q-proj tiles, else k-proj tiles.
__global__ void __launch_bounds__(256) gemm_proj_kernel(const float* __restrict__ queries,
                                                        const float* __restrict__ keys,
                                                        const float* __restrict__ Wq,
                                                        const float* __restrict__ Wk) {
    const int by = blockIdx.y;
    const int n0 = blockIdx.x * 64;
    if (by < (BB * QQ) / 64) {
        gemm_body(queries, Wq, g_qproj, HH, QS, by * 64, n0);
    } else {
        gemm_body(keys, Wk, g_kproj, HH, KSZ, (by - (BB * QQ) / 64) * 64, n0);
    }
}

// ---------------------------------------------------------------------------
// Fused flash partial: CTA = (split s, q-tile qt, batch b). grid (16,4,4).
// Split s owns k in {s, s+16, ..., s+16*63}; active count = ceil((vlen-s)/16).
// Phase 1: scores (lane-per-q, 8 k's per warp, tanh on MUFU).
// Phase 2: per-q max (smem reduce), exp, partial sums.
// Phase 3: P @ V with V staged in smem (reusing K buffer), v in registers.
// Emits per-split (m, S, O) partials for the combine kernel.
// ---------------------------------------------------------------------------
extern __shared__ float s_dyn[];

__global__ void __launch_bounds__(256) flash_kernel(const float* __restrict__ values,
                                                    const float* __restrict__ Wv,
                                                    const int* __restrict__ valid_lens32) {
    const int s = blockIdx.x;
    const int qt = blockIdx.y;
    const int b = blockIdx.z;
    const int tid = threadIdx.x;
    const int lane = tid & 31;
    const int wid = tid >> 5;

    // smem carve-up (floats)
    float* s_q = s_dyn;                          // 32*260 = 8320
    float* s_w = s_q + QTILE * 260;              // 256
    float* s_kv = s_w + 256;                     // 64*256 = 16384 (K, then V)
    float* s_p = s_kv + KPC * 256;               // 32*68 = 2176
    float* s_m = s_p + QTILE * PPAD;             // 8*32 = 256
    float* s_sig = s_m + 256;                    // 8*32 = 256
    float* s_mq = s_sig + 256;                   // 32

    const int vlen = load_vlen(valid_lens32, b);
    int cnt = (vlen - s + 15) >> 4;              // ceil((vlen-s)/16)
    if (cnt > KPC) cnt = KPC;

    const size_t prow = ((size_t)(s * BB + b)) * QQ + qt * QTILE;
    float* Obase = g_Opart + prow * DV;

    if (cnt <= 0) {   // whole split masked for this batch: emit neutral partial
#pragma unroll
        for (int q = 0; q < QTILE; q++) Obase[(size_t)q * DV + tid] = 0.0f;
        if (tid < QTILE) { g_mpart[prow + tid] = -1e30f; g_Spart[prow + tid] = 0.0f; }
        return;
    }

    // stage q tile (32x256) with pad-260 rows
    const float4* qbase = (const float4*)(g_qproj + ((size_t)(b * QQ + qt * QTILE)) * HH);
#pragma unroll
    for (int i = 0; i < 8; i++) {
        int idx = tid + i * 256;
        *(float4*)&s_q[(idx >> 6) * 260 + (idx & 63) * 4] = qbase[idx];
    }
    if (tid < 64) ((float4*)s_w)[tid] = ((const float4*)Wv)[tid];

    // stage K rows k = s + 16*j, j = 0..63 (always-valid memory)
    const float4* kp = (const float4*)(g_kproj + ((size_t)b * KK) * HH);
#pragma unroll
    for (int i = 0; i < 16; i++) {
        int idx = tid + i * 256;
        int j = idx >> 6, c = idx & 63;
        *(float4*)&s_kv[j * 256 + c * 4] = kp[(size_t)(s + 16 * j) * 64 + c];
    }
    __syncthreads();   // A

    // Phase 1: scores. warp wid owns j = wid*8 .. +8; lane = q.
    const float* sqrow = s_q + lane * 260;
    const float* sk = s_kv + wid * (8 * 256);
    float acc[8] = {};
#pragma unroll 2
    for (int h4 = 0; h4 < 64; h4++) {
        float4 qv = *(const float4*)&sqrow[h4 * 4];
        float4 wv = *(const float4*)&s_w[h4 * 4];
#pragma unroll
        for (int jj = 0; jj < 8; jj++) {
            float4 kv = *(const float4*)&sk[jj * 256 + h4 * 4];
            float a = acc[jj];
            a = fmaf(tanh_approx(qv.x + kv.x), wv.x, a);
            a = fmaf(tanh_approx(qv.y + kv.y), wv.y, a);
            a = fmaf(tanh_approx(qv.z + kv.z), wv.z, a);
            a = fmaf(tanh_approx(qv.w + kv.w), wv.w, a);
            acc[jj] = a;
        }
    }

    // Phase 2a: per-warp per-q max over valid j's
    float lmax = -1e30f;
#pragma unroll
    for (int jj = 0; jj < 8; jj++) {
        int j = wid * 8 + jj;
        if (j < cnt) lmax = fmaxf(lmax, acc[jj]);
    }
    s_m[wid * 32 + lane] = lmax;
    __syncthreads();   // B

    if (wid == 0) {
        float m = s_m[lane];
#pragma unroll
        for (int w = 1; w < 8; w++) m = fmaxf(m, s_m[w * 32 + lane]);
        s_mq[lane] = m;
    }
    __syncthreads();   // C

    // Phase 2b: exp, partial sums, stage p (q-major)
    const float mq = s_mq[lane];
    float p[8];
    float sig = 0.0f;
#pragma unroll
    for (int jj = 0; jj < 8; jj++) {
        int j = wid * 8 + jj;
        p[jj] = (j < cnt) ? __expf(acc[jj] - mq) : 0.0f;
        sig += p[jj];
    }
    s_sig[wid * 32 + lane] = sig;
    *(float4*)&s_p[lane * PPAD + wid * 8]     = make_float4(p[0], p[1], p[2], p[3]);
    *(float4*)&s_p[lane * PPAD + wid * 8 + 4] = make_float4(p[4], p[5], p[6], p[7]);
    __syncthreads();   // D (s_kv reads all done -> safe to overwrite below)

    if (wid == 0) {
        float S = s_sig[lane];
#pragma unroll
        for (int w = 1; w < 8; w++) S += s_sig[w * 32 + lane];
        g_mpart[prow + lane] = mq;
        g_Spart[prow + lane] = S;
    }

    // stage V rows k = s + 16*j into s_kv (reuse)
    const float4* vp = (const float4*)(values + ((size_t)b * KK) * DV);
#pragma unroll
    for (int i = 0; i < 16; i++) {
        int idx = tid + i * 256;
        int j = idx >> 6, c = idx & 63;
        *(float4*)&s_kv[j * 256 + c * 4] = vp[(size_t)(s + 16 * j) * 64 + c];
    }
    __syncthreads();   // E

    // Phase 3: O[q][dv] = sum_j p[q][j] * V[j][dv]. thread dv = wid*32+lane.
    const int dv = wid * 32 + lane;
    float v[KPC];
#pragma unroll
    for (int j = 0; j < KPC; j++) v[j] = s_kv[j * 256 + dv];

#pragma unroll 1
    for (int q = 0; q < QTILE; q++) {
        const float* pr = s_p + q * PPAD;
        float a0 = 0.f, a1 = 0.f, a2 = 0.f, a3 = 0.f;
#pragma unroll
        for (int j4 = 0; j4 < 16; j4++) {
            float4 pv = *(const float4*)&pr[j4 * 4];
            a0 = fmaf(pv.x, v[j4 * 4 + 0], a0);
            a1 = fmaf(pv.y, v[j4 * 4 + 1], a1);
            a2 = fmaf(pv.z, v[j4 * 4 + 2], a2);
            a3 = fmaf(pv.w, v[j4 * 4 + 3], a3);
        }
        Obase[(size_t)q * DV + dv] = (a0 + a1) + (a2 + a3);
    }
}

// ---------------------------------------------------------------------------
// Combine: out[b][q][:] = sum_s e^{m_s-M} O_s / sum_s e^{m_s-M} S_s.
// grid (QQ, BB) = 512 CTAs, 256 threads (dv).
// ---------------------------------------------------------------------------
__global__ void __launch_bounds__(256) combine_kernel(float* __restrict__ out) {
    const int q = blockIdx.x;
    const int b = blockIdx.y;
    const int tid = threadIdx.x;

    __shared__ float s_wt[SPLITS];

    if (tid < 32) {
        float m = -1e30f, S = 0.0f;
        if (tid < SPLITS) {
            size_t pidx = ((size_t)(tid * BB + b)) * QQ + q;
            m = g_mpart[pidx];
            S = g_Spart[pidx];
        }
        float M = m;
#pragma unroll
        for (int off = 16; off; off >>= 1)
            M = fmaxf(M, __shfl_xor_sync(0xffffffffu, M, off));
        float e = (m > -1e29f) ? __expf(m - M) : 0.0f;
        float d = e * S;
#pragma unroll
        for (int off = 16; off; off >>= 1)
            d += __shfl_xor_sync(0xffffffffu, d, off);
        if (tid < SPLITS) s_wt[tid] = e * __fdividef(1.0f, d);
    }
    __syncthreads();

    float acc = 0.0f;
#pragma unroll
    for (int s = 0; s < SPLITS; s++) {
        acc = fmaf(s_wt[s], g_Opart[(((size_t)(s * BB + b)) * QQ + q) * DV + tid], acc);
    }
    out[((size_t)(b * QQ + q)) * DV + tid] = acc;
}

// ---------------------------------------------------------------------------
// Launch
// ---------------------------------------------------------------------------
extern "C" void kernel_launch(void* const* d_in, const int* in_sizes, int n_in,
                              void* d_out, int out_size) {
    const float* queries = (const float*)d_in[0];
    const float* keys    = (const float*)d_in[1];
    const float* values  = (const float*)d_in[2];
    const int*   valid_lens = (const int*)d_in[3];
    const float* Wq = (const float*)d_in[4];
    const float* Wk = (const float*)d_in[5];
    const float* Wv = (const float*)d_in[6];
    float* out = (float*)d_out;

    (void)in_sizes; (void)n_in; (void)out_size;

    const int smem_bytes = (QTILE * 260 + 256 + KPC * 256 + QTILE * PPAD + 256 + 256 + 32) * 4;
    cudaFuncSetAttribute(flash_kernel, cudaFuncAttributeMaxDynamicSharedMemorySize, smem_bytes);

    gemm_proj_kernel<<<dim3(HH / 64, (BB * QQ) / 64 + (BB * KK) / 64), 256>>>(queries, keys, Wq, Wk);
    flash_kernel<<<dim3(SPLITS, QQ / QTILE, BB), 256, smem_bytes>>>(values, Wv, valid_lens);
    combine_kernel<<<dim3(QQ, BB), 256>>>(out);
}

// round 11
// speedup vs baseline: 2.2808x; 1.1494x over previous
#include <cuda_runtime.h>

// Problem shapes (fixed by the reference)
#define BB 4
#define QQ 128
#define KK 1024
#define HH 256
#define QS 256
#define KSZ 256
#define DV 256
#define SPLITS 16         // flash split-K factor (strided k assignment)
#define QTILE 32          // q's per flash CTA (lane = q)
#define KPC 64            // k's per flash CTA (= KK/SPLITS), 8 warps x 8
#define PPAD 68           // s_p row stride (q-major), multiple of 4

// Scratch (alloc-free rule: __device__ globals)
__device__ float g_qproj[BB * QQ * HH];                 // [B,Q,H]
__device__ float g_kproj[BB * KK * HH];                 // [B,K,H]
__device__ float g_Opart[SPLITS * BB * QQ * DV];        // per-split partial outputs
__device__ float g_mpart[SPLITS * BB * QQ];             // per-split row max
__device__ float g_Spart[SPLITS * BB * QQ];             // per-split exp-sum

// Robust valid_lens decode: reference says int64 but may materialize int32.
// valid_lens >= 1 always, so int64-LE viewed as int32 has zeros at odd slots.
__device__ __forceinline__ int load_vlen(const int* vl32, int b) {
    bool is64 = (vl32[1] == 0) && (vl32[3] == 0);
    return is64 ? vl32[2 * b] : vl32[b];
}

__device__ __forceinline__ float tanh_approx(float x) {
    float y;
    asm("tanh.approx.f32 %0, %1;" : "=f"(y) : "f"(x));
    return y;
}

// ---------------------------------------------------------------------------
// Projection GEMM: 128(M) x 64(N) tile, BK=16, 256 threads, 8x4 microtile.
// As stored transposed (As[kk][row]) so the microloop is 3x LDS.128 per 32 FMA.
// Register-prefetch double buffering.
// ---------------------------------------------------------------------------
__device__ __forceinline__ void gemm_body(const float* __restrict__ A,
                                          const float* __restrict__ Bm,
                                          float* __restrict__ C,
                                          int N, int K, int m0, int n0) {
    constexpr int BK = 16;
    __shared__ float As[BK][132];    // [kk][row], pad 132 -> conflict-free
    __shared__ float Bs[BK][64];     // [kk][col]

    const int tid = threadIdx.x;
    const int tx = tid & 15;         // 4 cols each
    const int ty = tid >> 4;         // 8 rows each

    float acc[8][4] = {};
    float a_reg[8], b_reg[4];

    // prefetch first tiles
#pragma unroll
    for (int i = 0; i < 8; i++) {
        int idx = tid + i * 256;
        a_reg[i] = A[(size_t)(m0 + (idx >> 4)) * K + (idx & 15)];
    }
#pragma unroll
    for (int i = 0; i < 4; i++) {
        int idx = tid + i * 256;
        b_reg[i] = Bm[(size_t)(idx >> 6) * N + (n0 + (idx & 63))];
    }

    for (int k0 = 0; k0 < K; k0 += BK) {
#pragma unroll
        for (int i = 0; i < 8; i++) {
            int idx = tid + i * 256;
            As[idx & 15][idx >> 4] = a_reg[i];   // transposed store
        }
#pragma unroll
        for (int i = 0; i < 4; i++) {
            int idx = tid + i * 256;
            Bs[idx >> 6][idx & 63] = b_reg[i];
        }
        __syncthreads();

        if (k0 + BK < K) {
#pragma unroll
            for (int i = 0; i < 8; i++) {
                int idx = tid + i * 256;
                a_reg[i] = A[(size_t)(m0 + (idx >> 4)) * K + (k0 + BK + (idx & 15))];
            }
#pragma unroll
            for (int i = 0; i < 4; i++) {
                int idx = tid + i * 256;
                b_reg[i] = Bm[(size_t)(k0 + BK + (idx >> 6)) * N + (n0 + (idx & 63))];
            }
        }

#pragma unroll
        for (int kk = 0; kk < BK; kk++) {
            float4 av0 = *(const float4*)&As[kk][ty * 8];
            float4 av1 = *(const float4*)&As[kk][ty * 8 + 4];
            float4 bv  = *(const float4*)&Bs[kk][tx * 4];
            float a[8] = {av0.x, av0.y, av0.z, av0.w, av1.x, av1.y, av1.z, av1.w};
            float b[4] = {bv.x, bv.y, bv.z, bv.w};
#pragma unroll
            for (int i = 0; i < 8; i++)
#pragma unroll
                for (int j = 0; j < 4; j++)
                    acc[i][j] = fmaf(a[i], b[j], acc[i][j]);
        }
        __syncthreads();
    }

#pragma unroll
    for (int i = 0; i < 8; i++) {
        float4 v = {acc[i][0], acc[i][1], acc[i][2], acc[i][3]};
        *(float4*)&C[(size_t)(m0 + ty * 8 + i) * N + (n0 + tx * 4)] = v;
    }
}

// Merged projections: blockIdx.y < 4 -> q-proj (M=512), else k-proj (M=4096).
// grid (HH/64=4, 4 + 32 = 36) = 144 CTAs (one wave).
__global__ void __launch_bounds__(256) gemm_proj_kernel(const float* __restrict__ queries,
                                                        const float* __restrict__ keys,
                                                        const float* __restrict__ Wq,
                                                        const float* __restrict__ Wk) {
    const int by = blockIdx.y;
    const int n0 = blockIdx.x * 64;
    if (by < (BB * QQ) / 128) {
        gemm_body(queries, Wq, g_qproj, HH, QS, by * 128, n0);
    } else {
        gemm_body(keys, Wk, g_kproj, HH, KSZ, (by - (BB * QQ) / 128) * 128, n0);
    }
}

// ---------------------------------------------------------------------------
// Fused flash partial: CTA = (split s, q-tile qt, batch b). grid (16,4,4).
// Split s owns k in {s, s+16, ..., s+16*63}; active count cnt = ceil((vlen-s)/16),
// which is contiguous in j -> per-warp work bounded by rem = cnt - wid*8.
// Phase 1: scores (lane-per-q, tanh on MUFU) ONLY for active j.
// Phase 2: per-q max (smem reduce), exp, partial sums.
// Phase 3: P @ V, V staged in smem (reusing K buffer), 16-j chunk guards.
// ---------------------------------------------------------------------------
extern __shared__ float s_dyn[];

__global__ void __launch_bounds__(256) flash_kernel(const float* __restrict__ values,
                                                    const float* __restrict__ Wv,
                                                    const int* __restrict__ valid_lens32) {
    const int s = blockIdx.x;
    const int qt = blockIdx.y;
    const int b = blockIdx.z;
    const int tid = threadIdx.x;
    const int lane = tid & 31;
    const int wid = tid >> 5;

    // smem carve-up (floats)
    float* s_q = s_dyn;                          // 32*260 = 8320
    float* s_w = s_q + QTILE * 260;              // 256
    float* s_kv = s_w + 256;                     // 64*256 = 16384 (K, then V)
    float* s_p = s_kv + KPC * 256;               // 32*68 = 2176
    float* s_m = s_p + QTILE * PPAD;             // 8*32 = 256
    float* s_sig = s_m + 256;                    // 8*32 = 256
    float* s_mq = s_sig + 256;                   // 32

    const int vlen = load_vlen(valid_lens32, b);
    int cnt = (vlen - s + 15) >> 4;              // ceil((vlen-s)/16)
    if (cnt > KPC) cnt = KPC;

    const size_t prow = ((size_t)(s * BB + b)) * QQ + qt * QTILE;
    float* Obase = g_Opart + prow * DV;

    if (cnt <= 0) {   // whole split masked for this batch: emit neutral partial
#pragma unroll
        for (int q = 0; q < QTILE; q++) Obase[(size_t)q * DV + tid] = 0.0f;
        if (tid < QTILE) { g_mpart[prow + tid] = -1e30f; g_Spart[prow + tid] = 0.0f; }
        return;
    }

    // stage q tile (32x256) with pad-260 rows
    const float4* qbase = (const float4*)(g_qproj + ((size_t)(b * QQ + qt * QTILE)) * HH);
#pragma unroll
    for (int i = 0; i < 8; i++) {
        int idx = tid + i * 256;
        *(float4*)&s_q[(idx >> 6) * 260 + (idx & 63) * 4] = qbase[idx];
    }
    if (tid < 64) ((float4*)s_w)[tid] = ((const float4*)Wv)[tid];

    // stage K rows k = s + 16*j for ACTIVE j only
    const float4* kp = (const float4*)(g_kproj + ((size_t)b * KK) * HH);
#pragma unroll
    for (int i = 0; i < 16; i++) {
        int idx = tid + i * 256;
        int j = idx >> 6, c = idx & 63;
        if (j < cnt)
            *(float4*)&s_kv[j * 256 + c * 4] = kp[(size_t)(s + 16 * j) * 64 + c];
    }
    __syncthreads();   // A

    // Phase 1: scores. warp wid owns j = wid*8 .. +8; lane = q.
    const float* sqrow = s_q + lane * 260;
    const float* sk = s_kv + wid * (8 * 256);
    float acc[8] = {};
    const int rem = cnt - wid * 8;               // active j's for this warp

    if (rem >= 8) {
#pragma unroll 2
        for (int h4 = 0; h4 < 64; h4++) {
            float4 qv = *(const float4*)&sqrow[h4 * 4];
            float4 wv = *(const float4*)&s_w[h4 * 4];
#pragma unroll
            for (int jj = 0; jj < 8; jj++) {
                float4 kv = *(const float4*)&sk[jj * 256 + h4 * 4];
                float a = acc[jj];
                a = fmaf(tanh_approx(qv.x + kv.x), wv.x, a);
                a = fmaf(tanh_approx(qv.y + kv.y), wv.y, a);
                a = fmaf(tanh_approx(qv.z + kv.z), wv.z, a);
                a = fmaf(tanh_approx(qv.w + kv.w), wv.w, a);
                acc[jj] = a;
            }
        }
    } else if (rem > 0) {
#pragma unroll 2
        for (int h4 = 0; h4 < 64; h4++) {
            float4 qv = *(const float4*)&sqrow[h4 * 4];
            float4 wv = *(const float4*)&s_w[h4 * 4];
#pragma unroll
            for (int jj = 0; jj < 8; jj++) {
                if (jj < rem) {
                    float4 kv = *(const float4*)&sk[jj * 256 + h4 * 4];
                    float a = acc[jj];
                    a = fmaf(tanh_approx(qv.x + kv.x), wv.x, a);
                    a = fmaf(tanh_approx(qv.y + kv.y), wv.y, a);
                    a = fmaf(tanh_approx(qv.z + kv.z), wv.z, a);
                    a = fmaf(tanh_approx(qv.w + kv.w), wv.w, a);
                    acc[jj] = a;
                }
            }
        }
    }
    // rem <= 0: skip phase 1 entirely (acc stays 0, masked below)

    // Phase 2a: per-warp per-q max over valid j's
    float lmax = -1e30f;
#pragma unroll
    for (int jj = 0; jj < 8; jj++) {
        if (jj < rem) lmax = fmaxf(lmax, acc[jj]);
    }
    s_m[wid * 32 + lane] = lmax;
    __syncthreads();   // B

    if (wid == 0) {
        float m = s_m[lane];
#pragma unroll
        for (int w = 1; w < 8; w++) m = fmaxf(m, s_m[w * 32 + lane]);
        s_mq[lane] = m;
    }
    __syncthreads();   // C

    // Phase 2b: exp, partial sums, stage p (q-major)
    const float mq = s_mq[lane];
    float p[8];
    float sig = 0.0f;
#pragma unroll
    for (int jj = 0; jj < 8; jj++) {
        p[jj] = (jj < rem) ? __expf(acc[jj] - mq) : 0.0f;
        sig += p[jj];
    }
    s_sig[wid * 32 + lane] = sig;
    *(float4*)&s_p[lane * PPAD + wid * 8]     = make_float4(p[0], p[1], p[2], p[3]);
    *(float4*)&s_p[lane * PPAD + wid * 8 + 4] = make_float4(p[4], p[5], p[6], p[7]);
    __syncthreads();   // D (s_kv reads all done -> safe to overwrite below)

    if (wid == 0) {
        float S = s_sig[lane];
#pragma unroll
        for (int w = 1; w < 8; w++) S += s_sig[w * 32 + lane];
        g_mpart[prow + lane] = mq;
        g_Spart[prow + lane] = S;
    }

    // stage V rows k = s + 16*j into s_kv (reuse), ACTIVE j only
    const float4* vp = (const float4*)(values + ((size_t)b * KK) * DV);
#pragma unroll
    for (int i = 0; i < 16; i++) {
        int idx = tid + i * 256;
        int j = idx >> 6, c = idx & 63;
        if (j < cnt)
            *(float4*)&s_kv[j * 256 + c * 4] = vp[(size_t)(s + 16 * j) * 64 + c];
    }
    __syncthreads();   // E

    // Phase 3: O[q][dv] = sum_j p[q][j] * V[j][dv]. thread dv = wid*32+lane.
    // 16-j chunks guarded by cnt (p is exactly 0 beyond cnt).
    const int dv = wid * 32 + lane;
    float v[KPC];
#pragma unroll
    for (int c = 0; c < 4; c++) {
        if (c * 16 < cnt) {
#pragma unroll
            for (int jj = 0; jj < 16; jj++) v[c * 16 + jj] = s_kv[(c * 16 + jj) * 256 + dv];
        }
    }

#pragma unroll 1
    for (int q = 0; q < QTILE; q++) {
        const float* pr = s_p + q * PPAD;
        float a0 = 0.f, a1 = 0.f, a2 = 0.f, a3 = 0.f;
#pragma unroll
        for (int c = 0; c < 4; c++) {
            if (c * 16 < cnt) {
#pragma unroll
                for (int j4 = c * 4; j4 < c * 4 + 4; j4++) {
                    float4 pv = *(const float4*)&pr[j4 * 4];
                    a0 = fmaf(pv.x, v[j4 * 4 + 0], a0);
                    a1 = fmaf(pv.y, v[j4 * 4 + 1], a1);
                    a2 = fmaf(pv.z, v[j4 * 4 + 2], a2);
                    a3 = fmaf(pv.w, v[j4 * 4 + 3], a3);
                }
            }
        }
        Obase[(size_t)q * DV + dv] = (a0 + a1) + (a2 + a3);
    }
}

// ---------------------------------------------------------------------------
// Combine: out[b][q][:] = sum_s e^{m_s-M} O_s / sum_s e^{m_s-M} S_s.
// grid (QQ, BB) = 512 CTAs, 256 threads (dv).
// ---------------------------------------------------------------------------
__global__ void __launch_bounds__(256) combine_kernel(float* __restrict__ out) {
    const int q = blockIdx.x;
    const int b = blockIdx.y;
    const int tid = threadIdx.x;

    __shared__ float s_wt[SPLITS];

    if (tid < 32) {
        float m = -1e30f, S = 0.0f;
        if (tid < SPLITS) {
            size_t pidx = ((size_t)(tid * BB + b)) * QQ + q;
            m = g_mpart[pidx];
            S = g_Spart[pidx];
        }
        float M = m;
#pragma unroll
        for (int off = 16; off; off >>= 1)
            M = fmaxf(M, __shfl_xor_sync(0xffffffffu, M, off));
        float e = (m > -1e29f) ? __expf(m - M) : 0.0f;
        float d = e * S;
#pragma unroll
        for (int off = 16; off; off >>= 1)
            d += __shfl_xor_sync(0xffffffffu, d, off);
        if (tid < SPLITS) s_wt[tid] = e * __fdividef(1.0f, d);
    }
    __syncthreads();

    float acc = 0.0f;
#pragma unroll
    for (int s = 0; s < SPLITS; s++) {
        acc = fmaf(s_wt[s], g_Opart[(((size_t)(s * BB + b)) * QQ + q) * DV + tid], acc);
    }
    out[((size_t)(b * QQ + q)) * DV + tid] = acc;
}

// ---------------------------------------------------------------------------
// Launch
// ---------------------------------------------------------------------------
extern "C" void kernel_launch(void* const* d_in, const int* in_sizes, int n_in,
                              void* d_out, int out_size) {
    const float* queries = (const float*)d_in[0];
    const float* keys    = (const float*)d_in[1];
    const float* values  = (const float*)d_in[2];
    const int*   valid_lens = (const int*)d_in[3];
    const float* Wq = (const float*)d_in[4];
    const float* Wk = (const float*)d_in[5];
    const float* Wv = (const float*)d_in[6];
    float* out = (float*)d_out;

    (void)in_sizes; (void)n_in; (void)out_size;

    const int smem_bytes = (QTILE * 260 + 256 + KPC * 256 + QTILE * PPAD + 256 + 256 + 32) * 4;
    cudaFuncSetAttribute(flash_kernel, cudaFuncAttributeMaxDynamicSharedMemorySize, smem_bytes);

    gemm_proj_kernel<<<dim3(HH / 64, (BB * QQ) / 128 + (BB * KK) / 128), 256>>>(queries, keys, Wq, Wk);
    flash_kernel<<<dim3(SPLITS, QQ / QTILE, BB), 256, smem_bytes>>>(values, Wv, valid_lens);
    combine_kernel<<<dim3(QQ, BB), 256>>>(out);
}